// round 9
// baseline (speedup 1.0000x reference)
#include <cuda_runtime.h>
#include <cuda_fp16.h>
#include <cuda_bf16.h>
#include <cstdint>

#define NN 100000
#define NE 1600000
#define TOT (NE + NN)
#define HD 128

union H2U { unsigned int u; __half2 h; };
__device__ __forceinline__ unsigned int h2_to_u(__half2 h) { H2U c; c.h = h; return c.u; }
__device__ __forceinline__ __half2 u_to_h2(unsigned int u) { H2U c; c.u = u; return c.h; }

__device__ __forceinline__ uint32_t f2tf(float f) {
    uint32_t r;
    asm("cvt.rna.tf32.f32 %0, %1;" : "=r"(r) : "f"(f));
    return r;
}

// ---------------- scratch (device globals; no allocation allowed) ------------
__device__ float4 g_hF[NN * 32];     // fp32 final h (input to GEMM2)
__device__ uint4  g_h0h[NN * 16];    // fp16 h0 (alpha term)
__device__ uint4  g_h16a[NN * 16];   // fp16 ping
__device__ uint4  g_h16b[NN * 16];   // fp16 pong
__device__ float  g_Wt1[128 * 128];  // W1 transposed [n][k]
__device__ float  g_Wt2[128 * 128];  // W2 transposed [n][k]
__device__ int    g_cnt[NN];
__device__ int    g_fill[NN];
__device__ float  g_dinv[NN];
__device__ int    g_rowptr[NN + 1];
__device__ int2   g_ew[TOT];         // .x = src col, .y = float bits of 0.9*w
__device__ int    g_bsum[64];
__device__ int    g_is64;

// ---------------- init counters + edge dtype detection -----------------------
__global__ void initdet(const int* ei32) {
    int n = blockIdx.x * blockDim.x + threadIdx.x;
    if (n < NN) { g_cnt[n] = 1; g_fill[n] = 0; }
    if (blockIdx.x == 0 && threadIdx.x < 32) {
        int lane = threadIdx.x;
        int orv = 0;
        for (int i = lane; i < 1024; i += 32) orv |= ei32[2 * i + 1];
        #pragma unroll
        for (int off = 16; off; off >>= 1) orv |= __shfl_xor_sync(0xFFFFFFFFu, orv, off);
        if (lane == 0) g_is64 = (orv == 0) ? 1 : 0;
    }
}

__device__ __forceinline__ int edge_src(const void* ei, int e) {
    if (g_is64) return (int)((const long long*)ei)[e];
    return ((const int*)ei)[e];
}
__device__ __forceinline__ int edge_dst(const void* ei, int e) {
    if (g_is64) return (int)((const long long*)ei)[NE + e];
    return ((const int*)ei)[NE + e];
}

__global__ void hist(const void* __restrict__ ei) {
    int e = blockIdx.x * blockDim.x + threadIdx.x;
    if (e < NE) atomicAdd(&g_cnt[edge_dst(ei, e)], 1);
}

__global__ void scan1() {
    __shared__ int sh[256];
    int tid = threadIdx.x;
    int base = blockIdx.x * 2048 + tid * 8;
    int v[8];
    int s = 0;
    #pragma unroll
    for (int i = 0; i < 8; i++) {
        int idx = base + i;
        v[i] = (idx < NN) ? g_cnt[idx] : 0;
        if (idx < NN) g_dinv[idx] = rsqrtf((float)v[i]);
        s += v[i];
    }
    sh[tid] = s;
    __syncthreads();
    for (int off = 1; off < 256; off <<= 1) {
        int t = (tid >= off) ? sh[tid - off] : 0;
        __syncthreads();
        sh[tid] += t;
        __syncthreads();
    }
    int run = sh[tid] - s;
    #pragma unroll
    for (int i = 0; i < 8; i++) {
        int idx = base + i;
        if (idx < NN) g_rowptr[idx] = run;
        run += v[i];
    }
    if (tid == 255) g_bsum[blockIdx.x] = sh[255];
}

__global__ void scanfix() {
    __shared__ int soff;
    int idx = blockIdx.x * blockDim.x + threadIdx.x;
    int sblk = (blockIdx.x * 256) >> 11;
    if (threadIdx.x == 0) {
        int a = 0;
        for (int i = 0; i < sblk; i++) a += g_bsum[i];
        soff = a;
    }
    __syncthreads();
    if (idx < NN) g_rowptr[idx] += soff;
    if (idx == 0) g_rowptr[NN] = TOT;
}

__global__ void scatter(const void* __restrict__ ei) {
    int e = blockIdx.x * blockDim.x + threadIdx.x;
    if (e < NE) {
        int s = edge_src(ei, e);
        int d = edge_dst(ei, e);
        int pos = g_rowptr[d] + atomicAdd(&g_fill[d], 1);
        float ww = 0.9f * g_dinv[s] * g_dinv[d];
        g_ew[pos] = make_int2(s, __float_as_int(ww));
    } else if (e < TOT) {
        int n = e - NE;
        int pos = g_rowptr[n] + atomicAdd(&g_fill[n], 1);
        float di = g_dinv[n];
        g_ew[pos] = make_int2(n, __float_as_int(0.9f * di * di));
    }
}

// ---------------- W transpose: Wt[n][k] = W[k][n] (128x128) ------------------
__global__ void transW(const float* __restrict__ W, float* __restrict__ Wt) {
    __shared__ float t[32][33];
    int bx = blockIdx.x & 3, by = blockIdx.x >> 2;
    int x = bx * 32 + threadIdx.x;
    int y = by * 32 + threadIdx.y;
    #pragma unroll
    for (int i = 0; i < 32; i += 8)
        t[threadIdx.y + i][threadIdx.x] = W[(y + i) * 128 + x];
    __syncthreads();
    int x2 = by * 32 + threadIdx.x;
    int y2 = bx * 32 + threadIdx.y;
    #pragma unroll
    for (int i = 0; i < 32; i += 8)
        Wt[(y2 + i) * 128 + x2] = t[threadIdx.x][threadIdx.y + i];
}

// ---------------- tf32 MMA GEMM: D = X @ W + b --------------------------------
// CTA 128x128 tile, 8 warps (4m x 2n), warp 32x64, mma.m16n8k8.tf32, K chunk 32.
#define LDT 36

__device__ __forceinline__ void mma_tf32(float* d, uint32_t a0, uint32_t a1,
                                         uint32_t a2, uint32_t a3,
                                         uint32_t b0, uint32_t b1) {
    asm volatile("mma.sync.aligned.m16n8k8.row.col.f32.tf32.tf32.f32 "
                 "{%0,%1,%2,%3}, {%4,%5,%6,%7}, {%8,%9}, {%0,%1,%2,%3};"
                 : "+f"(d[0]), "+f"(d[1]), "+f"(d[2]), "+f"(d[3])
                 : "r"(a0), "r"(a1), "r"(a2), "r"(a3), "r"(b0), "r"(b1));
}

__global__ __launch_bounds__(256, 2) void gemm_tf32(
    const float* __restrict__ X, const float* __restrict__ Wt,
    const float* __restrict__ bias, float* __restrict__ out, int mode)
{
    __shared__ uint32_t As[128 * LDT];   // [row][k] tf32 bits, chunk k=32
    __shared__ uint32_t Bs[128 * LDT];   // [n][k]   tf32 bits
    __shared__ float sb[128];

    int tid = threadIdx.x;
    int wid = tid >> 5;
    int lane = tid & 31;
    int rowBase = blockIdx.x * 128;

    if (tid < 128) sb[tid] = bias[tid];

    int wm = wid & 3;
    int wn = wid >> 2;
    int qr = lane >> 2;        // 0..7
    int qk = lane & 3;         // 0..3
    int qc = qk * 2;

    float acc[2][8][4];
    #pragma unroll
    for (int mt = 0; mt < 2; mt++)
        #pragma unroll
        for (int nt = 0; nt < 8; nt++)
            #pragma unroll
            for (int c = 0; c < 4; c++) acc[mt][nt][c] = 0.f;

    for (int kc = 0; kc < 4; kc++) {
        // A chunk: 128 rows x 32 k (1024 float4)
        #pragma unroll
        for (int l = 0; l < 4; l++) {
            int idx = tid + l * 256;
            int r = idx >> 3;
            int kq = idx & 7;
            float4 v = make_float4(0.f, 0.f, 0.f, 0.f);
            if (rowBase + r < NN)
                v = reinterpret_cast<const float4*>(X)[(rowBase + r) * 32 + kc * 8 + kq];
            uint4 u = make_uint4(f2tf(v.x), f2tf(v.y), f2tf(v.z), f2tf(v.w));
            *(uint4*)&As[r * LDT + kq * 4] = u;
        }
        // B chunk: 128 n x 32 k from Wt[n][k] (row-coalesced)
        #pragma unroll
        for (int l = 0; l < 4; l++) {
            int idx = tid + l * 256;
            int n = idx >> 3;
            int kq = idx & 7;
            float4 v = reinterpret_cast<const float4*>(Wt)[n * 32 + kc * 8 + kq];
            uint4 u = make_uint4(f2tf(v.x), f2tf(v.y), f2tf(v.z), f2tf(v.w));
            *(uint4*)&Bs[n * LDT + kq * 4] = u;
        }
        __syncthreads();

        #pragma unroll
        for (int s = 0; s < 4; s++) {
            int k0 = s * 8;
            uint32_t a[2][4], b[8][2];
            #pragma unroll
            for (int mt = 0; mt < 2; mt++) {
                int r = wm * 32 + mt * 16 + qr;
                const uint32_t* ap = &As[r * LDT + k0 + qk];
                a[mt][0] = ap[0];
                a[mt][1] = ap[8 * LDT];
                a[mt][2] = ap[4];
                a[mt][3] = ap[8 * LDT + 4];
            }
            #pragma unroll
            for (int nt = 0; nt < 8; nt++) {
                int n = wn * 64 + nt * 8 + qr;
                const uint32_t* bp = &Bs[n * LDT + k0 + qk];
                b[nt][0] = bp[0];
                b[nt][1] = bp[4];
            }
            #pragma unroll
            for (int mt = 0; mt < 2; mt++)
                #pragma unroll
                for (int nt = 0; nt < 8; nt++)
                    mma_tf32(acc[mt][nt], a[mt][0], a[mt][1], a[mt][2], a[mt][3],
                             b[nt][0], b[nt][1]);
        }
        __syncthreads();
    }

    // epilogue
    #pragma unroll
    for (int mt = 0; mt < 2; mt++) {
        #pragma unroll
        for (int nt = 0; nt < 8; nt++) {
            int c = wn * 64 + nt * 8 + qc;
            float bx = sb[c], by = sb[c + 1];
            int r0 = rowBase + wm * 32 + mt * 16 + qr;
            int r1 = r0 + 8;
            float d0 = acc[mt][nt][0] + bx, d1 = acc[mt][nt][1] + by;
            float d2 = acc[mt][nt][2] + bx, d3 = acc[mt][nt][3] + by;
            if (mode) {
                d0 = fmaxf(d0, 0.f); d1 = fmaxf(d1, 0.f);
                d2 = fmaxf(d2, 0.f); d3 = fmaxf(d3, 0.f);
                unsigned p0 = h2_to_u(__floats2half2_rn(d0, d1));
                unsigned p1 = h2_to_u(__floats2half2_rn(d2, d3));
                if (r0 < NN) {
                    ((unsigned*)g_h16a)[r0 * 64 + c / 2] = p0;
                    ((unsigned*)g_h0h)[r0 * 64 + c / 2] = p0;
                }
                if (r1 < NN) {
                    ((unsigned*)g_h16a)[r1 * 64 + c / 2] = p1;
                    ((unsigned*)g_h0h)[r1 * 64 + c / 2] = p1;
                }
            } else {
                if (r0 < NN) *(float2*)(out + r0 * HD + c) = make_float2(d0, d1);
                if (r1 < NN) *(float2*)(out + r1 * HD + c) = make_float2(d2, d3);
            }
        }
    }
}

// ---------------- APPNP propagation: 16 threads/node, uint4 fp16 gathers -----
__global__ __launch_bounds__(256) void propagate(int t) {
    int idx = blockIdx.x * blockDim.x + threadIdx.x;
    int node = idx >> 4;
    int lane = idx & 15;
    if (node >= NN) return;

    const uint4* __restrict__ hin = (t & 1) ? g_h16b : g_h16a;
    uint4* __restrict__ hout      = (t & 1) ? g_h16a : g_h16b;

    int beg = g_rowptr[node];
    int end = g_rowptr[node + 1];

    float a0 = 0.f, a1 = 0.f, a2 = 0.f, a3 = 0.f;
    float a4 = 0.f, a5 = 0.f, a6 = 0.f, a7 = 0.f;
    #pragma unroll 4
    for (int e = beg; e < end; e++) {
        int2 ew = __ldg(&g_ew[e]);
        float ww = __int_as_float(ew.y);
        uint4 hv = __ldg(&hin[ew.x * 16 + lane]);
        float2 f0 = __half22float2(u_to_h2(hv.x));
        float2 f1 = __half22float2(u_to_h2(hv.y));
        float2 f2 = __half22float2(u_to_h2(hv.z));
        float2 f3 = __half22float2(u_to_h2(hv.w));
        a0 = fmaf(ww, f0.x, a0); a1 = fmaf(ww, f0.y, a1);
        a2 = fmaf(ww, f1.x, a2); a3 = fmaf(ww, f1.y, a3);
        a4 = fmaf(ww, f2.x, a4); a5 = fmaf(ww, f2.y, a5);
        a6 = fmaf(ww, f3.x, a6); a7 = fmaf(ww, f3.y, a7);
    }

    uint4 zv = __ldg(&g_h0h[node * 16 + lane]);
    float2 z0 = __half22float2(u_to_h2(zv.x));
    float2 z1 = __half22float2(u_to_h2(zv.y));
    float2 z2 = __half22float2(u_to_h2(zv.z));
    float2 z3 = __half22float2(u_to_h2(zv.w));
    float o0 = a0 + 0.1f * z0.x, o1 = a1 + 0.1f * z0.y;
    float o2 = a2 + 0.1f * z1.x, o3 = a3 + 0.1f * z1.y;
    float o4 = a4 + 0.1f * z2.x, o5 = a5 + 0.1f * z2.y;
    float o6 = a6 + 0.1f * z3.x, o7 = a7 + 0.1f * z3.y;

    if (t == 9) {
        g_hF[node * 32 + lane * 2 + 0] = make_float4(o0, o1, o2, o3);
        g_hF[node * 32 + lane * 2 + 1] = make_float4(o4, o5, o6, o7);
    } else {
        uint4 u;
        u.x = h2_to_u(__floats2half2_rn(o0, o1));
        u.y = h2_to_u(__floats2half2_rn(o2, o3));
        u.z = h2_to_u(__floats2half2_rn(o4, o5));
        u.w = h2_to_u(__floats2half2_rn(o6, o7));
        hout[node * 16 + lane] = u;
    }
}

// ---------------- launch ------------------------------------------------------
extern "C" void kernel_launch(void* const* d_in, const int* in_sizes, int n_in,
                              void* d_out, int out_size) {
    const float* x  = (const float*)d_in[0];
    const void*  ei = d_in[1];
    const float* W1 = (const float*)d_in[2];
    const float* b1 = (const float*)d_in[3];
    const float* W2 = (const float*)d_in[4];
    const float* b2 = (const float*)d_in[5];
    float* out = (float*)d_out;

    void *p_hF = nullptr, *p_Wt1 = nullptr, *p_Wt2 = nullptr;
    cudaGetSymbolAddress(&p_hF, g_hF);
    cudaGetSymbolAddress(&p_Wt1, g_Wt1);
    cudaGetSymbolAddress(&p_Wt2, g_Wt2);

    const int T = 256;
    dim3 tb(32, 8);
    initdet<<<(NN + T - 1) / T, T>>>((const int*)ei);
    transW<<<16, tb>>>(W1, (float*)p_Wt1);
    transW<<<16, tb>>>(W2, (float*)p_Wt2);
    hist<<<(NE + T - 1) / T, T>>>(ei);
    scan1<<<(NN + 2047) / 2048, 256>>>();
    scanfix<<<(NN + T - 1) / T, T>>>();
    scatter<<<(TOT + T - 1) / T, T>>>(ei);

    gemm_tf32<<<(NN + 127) / 128, 256>>>(x, (const float*)p_Wt1, b1, nullptr, 1);

    for (int t = 0; t < 10; t++)
        propagate<<<(NN * 16 + T - 1) / T, T>>>(t);

    gemm_tf32<<<(NN + 127) / 128, 256>>>((const float*)p_hF, (const float*)p_Wt2, b2, out, 0);
}

// round 11
// speedup vs baseline: 1.2236x; 1.2236x over previous
#include <cuda_runtime.h>
#include <cuda_fp16.h>
#include <cstdint>

#define NN 100000
#define NE 1600000
#define TOT (NE + NN)
#define HD 128

union H2U { unsigned int u; __half2 h; };
__device__ __forceinline__ unsigned int h2_to_u(__half2 h) { H2U c; c.h = h; return c.u; }
__device__ __forceinline__ __half2 u_to_h2(unsigned int u) { H2U c; c.u = u; return c.h; }

// ---------------- scratch (device globals; no allocation allowed) ------------
__device__ float4 g_hF[NN * 32];     // fp32 final h (input to GEMM2)
__device__ uint4  g_h16a[NN * 16];   // fp16 h0 (alpha term, written by gemm1)
__device__ uint4  g_h16b[NN * 16];   // fp16 ping
__device__ uint4  g_h16c[NN * 16];   // fp16 pong
__device__ int    g_cnt[NN];
__device__ int    g_fill[NN];
__device__ float  g_dinv[NN];
__device__ int    g_rowptr[NN + 1];
__device__ int2   g_ew[TOT];         // .x = src col, .y = float bits of 0.9*w
__device__ int    g_bsum[64];
__device__ int    g_is64;

// ---------------- init counters + edge dtype detection -----------------------
__global__ void initdet(const int* ei32) {
    int n = blockIdx.x * blockDim.x + threadIdx.x;
    if (n < NN) { g_cnt[n] = 1; g_fill[n] = 0; }
    if (blockIdx.x == 0 && threadIdx.x < 32) {
        int lane = threadIdx.x;
        int orv = 0;
        for (int i = lane; i < 1024; i += 32) orv |= ei32[2 * i + 1];
        #pragma unroll
        for (int off = 16; off; off >>= 1) orv |= __shfl_xor_sync(0xFFFFFFFFu, orv, off);
        if (lane == 0) g_is64 = (orv == 0) ? 1 : 0;
    }
}

__device__ __forceinline__ int edge_src(const void* ei, int e) {
    if (g_is64) return (int)((const long long*)ei)[e];
    return ((const int*)ei)[e];
}
__device__ __forceinline__ int edge_dst(const void* ei, int e) {
    if (g_is64) return (int)((const long long*)ei)[NE + e];
    return ((const int*)ei)[NE + e];
}

__global__ void hist(const void* __restrict__ ei) {
    int e = blockIdx.x * blockDim.x + threadIdx.x;
    if (e < NE) atomicAdd(&g_cnt[edge_dst(ei, e)], 1);
}

__global__ void scan1() {
    __shared__ int sh[256];
    int tid = threadIdx.x;
    int base = blockIdx.x * 2048 + tid * 8;
    int v[8];
    int s = 0;
    #pragma unroll
    for (int i = 0; i < 8; i++) {
        int idx = base + i;
        v[i] = (idx < NN) ? g_cnt[idx] : 0;
        if (idx < NN) g_dinv[idx] = rsqrtf((float)v[i]);
        s += v[i];
    }
    sh[tid] = s;
    __syncthreads();
    for (int off = 1; off < 256; off <<= 1) {
        int t = (tid >= off) ? sh[tid - off] : 0;
        __syncthreads();
        sh[tid] += t;
        __syncthreads();
    }
    int run = sh[tid] - s;
    #pragma unroll
    for (int i = 0; i < 8; i++) {
        int idx = base + i;
        if (idx < NN) g_rowptr[idx] = run;
        run += v[i];
    }
    if (tid == 255) g_bsum[blockIdx.x] = sh[255];
}

__global__ void scanfix() {
    __shared__ int soff;
    int idx = blockIdx.x * blockDim.x + threadIdx.x;
    int sblk = (blockIdx.x * 256) >> 11;
    if (threadIdx.x == 0) {
        int a = 0;
        for (int i = 0; i < sblk; i++) a += g_bsum[i];
        soff = a;
    }
    __syncthreads();
    if (idx < NN) g_rowptr[idx] += soff;
    if (idx == 0) g_rowptr[NN] = TOT;
}

__global__ void scatter(const void* __restrict__ ei) {
    int e = blockIdx.x * blockDim.x + threadIdx.x;
    if (e < NE) {
        int s = edge_src(ei, e);
        int d = edge_dst(ei, e);
        int pos = g_rowptr[d] + atomicAdd(&g_fill[d], 1);
        float ww = 0.9f * g_dinv[s] * g_dinv[d];
        g_ew[pos] = make_int2(s, __float_as_int(ww));
    } else if (e < TOT) {
        int n = e - NE;
        int pos = g_rowptr[n] + atomicAdd(&g_fill[n], 1);
        float di = g_dinv[n];
        g_ew[pos] = make_int2(n, __float_as_int(0.9f * di * di));
    }
}

// ---------------- 128-tile fp32 SGEMM ----------------------------------------
// mode 0: plain fp32 out.  mode 1: relu, write fp16 h0 to g_h16a only.
__global__ __launch_bounds__(256) void gemm128(
    const float* __restrict__ X, const float* __restrict__ Wm,
    const float* __restrict__ bias, float* __restrict__ out, int mode)
{
    __shared__ float As[128][33];
    __shared__ float Bs[32][128];

    int tid = threadIdx.x;
    int tx = tid & 15;
    int ty = tid >> 4;
    int rowBase = blockIdx.x * 128;

    float acc[64];
    #pragma unroll
    for (int i = 0; i < 64; i++) acc[i] = 0.0f;

    for (int kc = 0; kc < 4; kc++) {
        #pragma unroll
        for (int l = 0; l < 4; l++) {
            int idx = tid + l * 256;
            int r  = idx >> 3;
            int kq = idx & 7;
            float4 v = make_float4(0.f, 0.f, 0.f, 0.f);
            int row = rowBase + r;
            if (row < NN)
                v = reinterpret_cast<const float4*>(X)[row * 32 + kc * 8 + kq];
            As[r][kq * 4 + 0] = v.x;
            As[r][kq * 4 + 1] = v.y;
            As[r][kq * 4 + 2] = v.z;
            As[r][kq * 4 + 3] = v.w;
        }
        #pragma unroll
        for (int l = 0; l < 4; l++) {
            int idx = tid + l * 256;
            int k  = idx >> 5;
            int cq = idx & 31;
            reinterpret_cast<float4*>(&Bs[k][0])[cq] =
                reinterpret_cast<const float4*>(Wm)[(kc * 32 + k) * 32 + cq];
        }
        __syncthreads();

        #pragma unroll
        for (int k = 0; k < 32; k++) {
            float b0[8], a0[8];
            *(float4*)&b0[0] = *(const float4*)&Bs[k][tx * 8];
            *(float4*)&b0[4] = *(const float4*)&Bs[k][tx * 8 + 4];
            #pragma unroll
            for (int i = 0; i < 8; i++) a0[i] = As[ty * 8 + i][k];
            #pragma unroll
            for (int i = 0; i < 8; i++)
                #pragma unroll
                for (int j = 0; j < 8; j++)
                    acc[i * 8 + j] = fmaf(a0[i], b0[j], acc[i * 8 + j]);
        }
        __syncthreads();
    }

    float bb[8];
    *(float4*)&bb[0] = *(const float4*)&bias[tx * 8];
    *(float4*)&bb[4] = *(const float4*)&bias[tx * 8 + 4];

    #pragma unroll
    for (int i = 0; i < 8; i++) {
        int row = rowBase + ty * 8 + i;
        if (row < NN) {
            float o[8];
            #pragma unroll
            for (int j = 0; j < 8; j++) o[j] = acc[i * 8 + j] + bb[j];
            if (mode) {
                #pragma unroll
                for (int j = 0; j < 8; j++) o[j] = fmaxf(o[j], 0.f);
                uint4 u;
                u.x = h2_to_u(__floats2half2_rn(o[0], o[1]));
                u.y = h2_to_u(__floats2half2_rn(o[2], o[3]));
                u.z = h2_to_u(__floats2half2_rn(o[4], o[5]));
                u.w = h2_to_u(__floats2half2_rn(o[6], o[7]));
                g_h16a[row * 16 + tx] = u;   // tx covers 8 cols = exactly 1 uint4
            } else {
                float4* op = reinterpret_cast<float4*>(out + row * HD + tx * 8);
                op[0] = *(float4*)&o[0];
                op[1] = *(float4*)&o[4];
            }
        }
    }
}

// ---------------- APPNP propagation: 16 threads/node, uint4 fp16 gathers -----
// t=0: in=g_h16a(h0). t>=1: in = (t odd ? g_h16b : g_h16c).
// out = (t odd ? g_h16c : g_h16b); t==9 writes fp32 g_hF.
// alpha term always from g_h16a.
__global__ __launch_bounds__(256) void propagate(int t) {
    int idx = blockIdx.x * blockDim.x + threadIdx.x;
    int node = idx >> 4;
    int lane = idx & 15;
    if (node >= NN) return;

    const uint4* __restrict__ hin =
        (t == 0) ? g_h16a : ((t & 1) ? g_h16b : g_h16c);
    uint4* __restrict__ hout = (t & 1) ? g_h16c : g_h16b;

    int beg = g_rowptr[node];
    int end = g_rowptr[node + 1];

    float a0 = 0.f, a1 = 0.f, a2 = 0.f, a3 = 0.f;
    float a4 = 0.f, a5 = 0.f, a6 = 0.f, a7 = 0.f;
    #pragma unroll 4
    for (int e = beg; e < end; e++) {
        int2 ew = __ldg(&g_ew[e]);
        float ww = __int_as_float(ew.y);
        uint4 hv = __ldg(&hin[ew.x * 16 + lane]);
        float2 f0 = __half22float2(u_to_h2(hv.x));
        float2 f1 = __half22float2(u_to_h2(hv.y));
        float2 f2 = __half22float2(u_to_h2(hv.z));
        float2 f3 = __half22float2(u_to_h2(hv.w));
        a0 = fmaf(ww, f0.x, a0); a1 = fmaf(ww, f0.y, a1);
        a2 = fmaf(ww, f1.x, a2); a3 = fmaf(ww, f1.y, a3);
        a4 = fmaf(ww, f2.x, a4); a5 = fmaf(ww, f2.y, a5);
        a6 = fmaf(ww, f3.x, a6); a7 = fmaf(ww, f3.y, a7);
    }

    uint4 zv = __ldg(&g_h16a[node * 16 + lane]);
    float2 z0 = __half22float2(u_to_h2(zv.x));
    float2 z1 = __half22float2(u_to_h2(zv.y));
    float2 z2 = __half22float2(u_to_h2(zv.z));
    float2 z3 = __half22float2(u_to_h2(zv.w));
    float o0 = a0 + 0.1f * z0.x, o1 = a1 + 0.1f * z0.y;
    float o2 = a2 + 0.1f * z1.x, o3 = a3 + 0.1f * z1.y;
    float o4 = a4 + 0.1f * z2.x, o5 = a5 + 0.1f * z2.y;
    float o6 = a6 + 0.1f * z3.x, o7 = a7 + 0.1f * z3.y;

    if (t == 9) {
        g_hF[node * 32 + lane * 2 + 0] = make_float4(o0, o1, o2, o3);
        g_hF[node * 32 + lane * 2 + 1] = make_float4(o4, o5, o6, o7);
    } else {
        uint4 u;
        u.x = h2_to_u(__floats2half2_rn(o0, o1));
        u.y = h2_to_u(__floats2half2_rn(o2, o3));
        u.z = h2_to_u(__floats2half2_rn(o4, o5));
        u.w = h2_to_u(__floats2half2_rn(o6, o7));
        hout[node * 16 + lane] = u;
    }
}

// ---------------- launch ------------------------------------------------------
static cudaStream_t s_gemm = nullptr;
static cudaEvent_t  s_fork = nullptr, s_join = nullptr;

extern "C" void kernel_launch(void* const* d_in, const int* in_sizes, int n_in,
                              void* d_out, int out_size) {
    const float* x  = (const float*)d_in[0];
    const void*  ei = d_in[1];
    const float* W1 = (const float*)d_in[2];
    const float* b1 = (const float*)d_in[3];
    const float* W2 = (const float*)d_in[4];
    const float* b2 = (const float*)d_in[5];
    float* out = (float*)d_out;

    void* p_hF = nullptr;
    cudaGetSymbolAddress(&p_hF, g_hF);

    // one-time host resource setup (first call is the uncaptured correctness run)
    if (!s_gemm) {
        cudaStreamCreateWithFlags(&s_gemm, cudaStreamNonBlocking);
        cudaEventCreateWithFlags(&s_fork, cudaEventDisableTiming);
        cudaEventCreateWithFlags(&s_join, cudaEventDisableTiming);
    }

    const int T = 256;

    // fork: gemm1 runs concurrently with the CSR build chain
    cudaEventRecord(s_fork, 0);
    cudaStreamWaitEvent(s_gemm, s_fork, 0);
    gemm128<<<(NN + 127) / 128, 256, 0, s_gemm>>>(x, W1, b1, nullptr, 1);
    cudaEventRecord(s_join, s_gemm);

    initdet<<<(NN + T - 1) / T, T>>>((const int*)ei);
    hist<<<(NE + T - 1) / T, T>>>(ei);
    scan1<<<(NN + 2047) / 2048, 256>>>();
    scanfix<<<(NN + T - 1) / T, T>>>();
    scatter<<<(TOT + T - 1) / T, T>>>(ei);

    // join before propagation (needs both h0 and CSR)
    cudaStreamWaitEvent(0, s_join, 0);

    for (int t = 0; t < 10; t++)
        propagate<<<(NN * 16 + T - 1) / T, T>>>(t);

    gemm128<<<(NN + 127) / 128, 256>>>((const float*)p_hF, W2, b2, out, 0);
}